// round 3
// baseline (speedup 1.0000x reference)
#include <cuda_runtime.h>

// Row-wise L1 normalization: y[b,r,:] = x[b,r,:] / max(sum(x[b,r,:]), 1e-5)
// [16, 2048, 2048] fp32. One WARP per row; each warp loops over ROWS_PER_WARP
// rows so that row i's stores (issue-only) cover row i+1's load latency.
// 32 lanes x 16 float4 = 2048 floats per row, fully register-resident.

#define ROW_LEN 2048
#define V4_PER_ROW (ROW_LEN / 4)       // 512
#define V4_PER_LANE (V4_PER_ROW / 32)  // 16
#define WARPS_PER_CTA 8
#define THREADS (WARPS_PER_CTA * 32)
#define ROWS_PER_WARP 4
#define N_ROWS (16 * 2048)             // 32768
#define GRID (N_ROWS / (WARPS_PER_CTA * ROWS_PER_WARP))  // 1024

__global__ __launch_bounds__(THREADS, 3)
void rownorm_loop_kernel(const float4* __restrict__ in, float4* __restrict__ out) {
    const int warp0 = blockIdx.x * WARPS_PER_CTA + (threadIdx.x >> 5);
    const int lane = threadIdx.x & 31;
    const int total_warps = GRID * WARPS_PER_CTA;   // 8192

    #pragma unroll 1
    for (int r = 0; r < ROWS_PER_WARP; r++) {
        const int row = warp0 + r * total_warps;
        const long long base = (long long)row * V4_PER_ROW + lane;

        // Front-batched streaming loads (MLP up to 16).
        float4 v[V4_PER_LANE];
        #pragma unroll
        for (int i = 0; i < V4_PER_LANE; i++)
            v[i] = __ldcs(&in[base + i * 32]);

        float s = 0.0f;
        #pragma unroll
        for (int i = 0; i < V4_PER_LANE; i++)
            s += (v[i].x + v[i].y) + (v[i].z + v[i].w);

        #pragma unroll
        for (int o = 16; o > 0; o >>= 1)
            s += __shfl_xor_sync(0xffffffffu, s, o);

        const float inv = 1.0f / fmaxf(s, 1e-5f);

        #pragma unroll
        for (int i = 0; i < V4_PER_LANE; i++) {
            float4 w = v[i];
            w.x *= inv; w.y *= inv; w.z *= inv; w.w *= inv;
            __stcs(&out[base + i * 32], w);
        }
    }
}

extern "C" void kernel_launch(void* const* d_in, const int* in_sizes, int n_in,
                              void* d_out, int out_size) {
    const float4* in = (const float4*)d_in[0];
    float4* out = (float4*)d_out;
    rownorm_loop_kernel<<<GRID, THREADS>>>(in, out);
}